// round 2
// baseline (speedup 1.0000x reference)
#include <cuda_runtime.h>

// PCNN recurrence: B=32, T=64, L=8192.
// Trapezoidal tiling: each block owns a SEG=1024 slice of one batch row and
// computes a W=SEG+2H region (H=64 halo) for all T steps with no inter-block
// communication. Validity cone [a+t-1, b-t+1) still covers [s0,s1) at t=T.
// State f,l,e,y lives in registers (4 elems/thread); y is exchanged through a
// double-buffered shared array (1 barrier per step).

#define Tn  64
#define Ln  8192
#define Bn  32
#define SEG 1024
#define Hh  64
#define Wn  (SEG + 2 * Hh)   // 1152
#define NTHREADS (Wn / 4)    // 288

__global__ __launch_bounds__(NTHREADS)
void pcnn_kernel(const float* __restrict__ x,
                 const float* __restrict__ w,
                 float* __restrict__ out)
{
    const int seg = blockIdx.x;
    const int b   = blockIdx.y;
    const int tid = threadIdx.x;

    const int s0 = seg * SEG;         // owned segment [s0, s0+SEG)
    const int a  = s0 - Hh;           // compute region start
    const int p0 = a + 4 * tid;       // first of this thread's 4 positions

    const float w0 = __ldg(&w[0]);
    const float w1 = __ldg(&w[1]);
    const float w2 = __ldg(&w[2]);

    const float df = 0.90483741803595952f;  // exp(-0.1)
    const float dl = 0.36787944117144233f;  // exp(-1)
    const float de = 0.36787944117144233f;  // exp(-1)
    const float Ve = 10.0f;

    // Group-aligned predicates (all boundaries are multiples of 4)
    const bool inL   = (p0 >= 0) && (p0 < Ln);
    const bool inSeg = (p0 >= s0) && (p0 < s0 + SEG);

    __shared__ float ybuf[2][Wn + 8];
    float* cur = &ybuf[0][4];
    float* nxt = &ybuf[1][4];

    // y_0 = 0 everywhere; borders (region-exterior neighbors) stay 0 forever.
    *(float4*)(cur + 4 * tid) = make_float4(0.f, 0.f, 0.f, 0.f);
    if (tid == 0) {
        cur[-1] = 0.f; cur[Wn] = 0.f;
        nxt[-1] = 0.f; nxt[Wn] = 0.f;
    }

    float f0 = 0.f, f1 = 0.f, f2 = 0.f, f3 = 0.f;
    float l0 = 0.f, l1 = 0.f, l2 = 0.f, l3 = 0.f;
    float e0 = 10.f, e1 = 10.f, e2 = 10.f, e3 = 10.f;  // V_E / ALPHA_E
    float y0 = 0.f, y1 = 0.f, y2 = 0.f, y3 = 0.f;

    const float4* xbase = (const float4*)(x   + (size_t)(b * Tn) * Ln);
    float4*       obase = (float4*)      (out + (size_t)(b * Tn) * Ln);
    const int v4 = p0 >> 2;  // float4 index within a row (valid when inL)

    float4 xv = inL ? __ldg(xbase + v4) : make_float4(0.f, 0.f, 0.f, 0.f);
    __syncthreads();

#pragma unroll 1
    for (int t = 0; t < Tn; ++t) {
        // Prefetch next step's x while this step computes.
        float4 xn = make_float4(0.f, 0.f, 0.f, 0.f);
        if (t + 1 < Tn && inL)
            xn = __ldg(xbase + (size_t)(t + 1) * (Ln / 4) + v4);

        const float yl = cur[4 * tid - 1];
        const float yr = cur[4 * tid + 4];

        // One PCNN step for one element; updates f,l,e in place, returns new y.
        auto onestep = [&](float& f, float& l, float& e,
                           float y, float ym, float yp, float xj) -> float {
            const float conv = fmaf(w0, ym, fmaf(w1, y, w2 * yp));
            f = fmaf(df, f, xj) + conv;
            l = fmaf(dl, l, ym + yp);
            const float u = f * fmaf(0.5f, l, 1.0f);
            e = fmaf(de, e, Ve * y);
            const float z = u - e;
            return __fdividef(1.0f, 1.0f + __expf(-z));
        };

        float ny0 = onestep(f0, l0, e0, y0, yl, y1, xv.x);
        float ny1 = onestep(f1, l1, e1, y1, y0, y2, xv.y);
        float ny2 = onestep(f2, l2, e2, y2, y1, y3, xv.z);
        float ny3 = onestep(f3, l3, e3, y3, y2, yr, xv.w);

        // Positions outside [0, L) behave as the zero pad: force y = 0.
        if (!inL) { ny0 = 0.f; ny1 = 0.f; ny2 = 0.f; ny3 = 0.f; }

        if (inSeg)
            obase[(size_t)t * (Ln / 4) + v4] = make_float4(ny0, ny1, ny2, ny3);

        *(float4*)(nxt + 4 * tid) = make_float4(ny0, ny1, ny2, ny3);
        __syncthreads();

        // Rotate buffers / state.
        float* tmp = cur; cur = nxt; nxt = tmp;
        y0 = ny0; y1 = ny1; y2 = ny2; y3 = ny3;
        xv = xn;
    }
}

extern "C" void kernel_launch(void* const* d_in, const int* in_sizes, int n_in,
                              void* d_out, int out_size)
{
    const float* x = (const float*)d_in[0];   // [32, 64, 8192] f32
    const float* w = (const float*)d_in[1];   // [3] f32
    float* out = (float*)d_out;               // [32, 64, 8192] f32

    dim3 grid(Ln / SEG, Bn);   // (8, 32) = 256 blocks
    pcnn_kernel<<<grid, NTHREADS>>>(x, w, out);
}

// round 3
// speedup vs baseline: 1.0557x; 1.0557x over previous
#include <cuda_runtime.h>

// PCNN recurrence: B=32, T=64, L=8192.
// Trapezoidal tiling: each block owns a SEG=512 slice of one batch row and
// computes a W=SEG+2H region (H=64 halo) for all T steps with no inter-block
// communication. Validity cone [a+t-1, b-t+1) still covers [s0,s1) at t=T.
// 2 elems/thread -> 512 blocks x 10 warps => ~35 warps/SM (vs 15.6 before).

#define Tn  64
#define Ln  8192
#define Bn  32
#define SEG 512
#define Hh  64
#define Wn  (SEG + 2 * Hh)   // 640
#define NTHREADS (Wn / 2)    // 320

__global__ __launch_bounds__(NTHREADS)
void pcnn_kernel(const float* __restrict__ x,
                 const float* __restrict__ w,
                 float* __restrict__ out)
{
    const int seg = blockIdx.x;
    const int b   = blockIdx.y;
    const int tid = threadIdx.x;

    const int s0 = seg * SEG;         // owned segment [s0, s0+SEG)
    const int a  = s0 - Hh;           // compute region start
    const int p0 = a + 2 * tid;       // first of this thread's 2 positions

    const float w0 = __ldg(&w[0]);
    const float w1 = __ldg(&w[1]);
    const float w2 = __ldg(&w[2]);

    const float df = 0.90483741803595952f;  // exp(-0.1)
    const float dl = 0.36787944117144233f;  // exp(-1)
    const float de = 0.36787944117144233f;  // exp(-1)
    const float Ve = 10.0f;

    // Pair-aligned predicates (all boundaries are even)
    const bool inL   = (p0 >= 0) && (p0 < Ln);
    const bool inSeg = (p0 >= s0) && (p0 < s0 + SEG);

    __shared__ float ybuf[2][Wn + 8];
    float* cur = &ybuf[0][4];
    float* nxt = &ybuf[1][4];

    // y_0 = 0 everywhere; region-exterior neighbors stay 0 forever.
    *(float2*)(cur + 2 * tid) = make_float2(0.f, 0.f);
    if (tid == 0) {
        cur[-1] = 0.f; cur[Wn] = 0.f;
        nxt[-1] = 0.f; nxt[Wn] = 0.f;
    }

    float f0 = 0.f, f1 = 0.f;
    float l0 = 0.f, l1 = 0.f;
    float e0 = 10.f, e1 = 10.f;      // V_E / ALPHA_E
    float y0 = 0.f, y1 = 0.f;

    const float2* xbase = (const float2*)(x   + (size_t)(b * Tn) * Ln);
    float2*       obase = (float2*)      (out + (size_t)(b * Tn) * Ln);
    const int v2 = p0 >> 1;  // float2 index within a row (valid when inL)

    float2 xv = inL ? __ldg(xbase + v2) : make_float2(0.f, 0.f);
    __syncthreads();

#pragma unroll 1
    for (int t = 0; t < Tn; ++t) {
        // Prefetch next step's x while this step computes.
        float2 xn = make_float2(0.f, 0.f);
        if (t + 1 < Tn && inL)
            xn = __ldg(xbase + (size_t)(t + 1) * (Ln / 2) + v2);

        const float yl = cur[2 * tid - 1];
        const float yr = cur[2 * tid + 2];

        // One PCNN step for one element; updates f,l,e in place, returns new y.
        auto onestep = [&](float& f, float& l, float& e,
                           float y, float ym, float yp, float xj) -> float {
            const float conv = fmaf(w0, ym, fmaf(w1, y, w2 * yp));
            f = fmaf(df, f, xj) + conv;
            l = fmaf(dl, l, ym + yp);
            const float u = f * fmaf(0.5f, l, 1.0f);
            e = fmaf(de, e, Ve * y);
            const float z = u - e;
            return __fdividef(1.0f, 1.0f + __expf(-z));
        };

        float ny0 = onestep(f0, l0, e0, y0, yl, y1, xv.x);
        float ny1 = onestep(f1, l1, e1, y1, y0, yr, xv.y);

        // Positions outside [0, L) behave as the zero pad: force y = 0.
        if (!inL) { ny0 = 0.f; ny1 = 0.f; }

        if (inSeg)
            obase[(size_t)t * (Ln / 2) + v2] = make_float2(ny0, ny1);

        *(float2*)(nxt + 2 * tid) = make_float2(ny0, ny1);
        __syncthreads();

        // Rotate buffers / state.
        float* tmp = cur; cur = nxt; nxt = tmp;
        y0 = ny0; y1 = ny1;
        xv = xn;
    }
}

extern "C" void kernel_launch(void* const* d_in, const int* in_sizes, int n_in,
                              void* d_out, int out_size)
{
    const float* x = (const float*)d_in[0];   // [32, 64, 8192] f32
    const float* w = (const float*)d_in[1];   // [3] f32
    float* out = (float*)d_out;               // [32, 64, 8192] f32

    dim3 grid(Ln / SEG, Bn);   // (16, 32) = 512 blocks
    pcnn_kernel<<<grid, NTHREADS>>>(x, w, out);
}

// round 4
// speedup vs baseline: 1.3851x; 1.3120x over previous
#include <cuda_runtime.h>

// PCNN recurrence B=32, T=64, L=8192 — time-chunked warp-autonomous trapezoids.
//
// Block owns SEG=1024 of one batch row; computes region WR=1184 (halo 80/side =
// 64 for T steps + 16 warp slack). T split into 4 chunks of TC=16 steps.
// Within a chunk each warp is autonomous: 128 contiguous y elems in registers
// (4/thread), neighbor exchange via 2 shuffles/step, valid cone shrinks 1/step
// so after 16 steps the central 96 elems are exact. Warps overlap by 32; y is
// re-exchanged through SMEM only at chunk boundaries (2 barriers/chunk, 8 total
// vs 64 before). f,l,e state stays in registers the whole time.

#define Tn   64
#define Ln   8192
#define Bn   32
#define SEG  1024
#define TC   16
#define NW   12                 // warps per block
#define WR   (96 * NW + 32)     // 1184 region cells
#define NTH  (NW * 32)          // 384

__global__ __launch_bounds__(NTH)
void pcnn_kernel(const float* __restrict__ x,
                 const float* __restrict__ w,
                 float* __restrict__ out)
{
    const int tid  = threadIdx.x;
    const int warp = tid >> 5;
    const int lane = tid & 31;
    const int b    = blockIdx.y;
    const int s0   = blockIdx.x * SEG;
    const int r0   = s0 - 80;              // region origin (abs)
    const int off  = 96 * warp + 4 * lane; // region-rel base of this thread's 4 elems
    const int q0   = r0 + off;             // absolute position of elem 0

    const float w0 = __ldg(&w[0]);
    const float w1 = __ldg(&w[1]);
    const float w2 = __ldg(&w[2]);

    const float df = 0.90483741803595952f;  // exp(-0.1)
    const float dl = 0.36787944117144233f;  // exp(-1)
    const float de = 0.36787944117144233f;  // exp(-1)
    const float Ve = 10.0f;

    // All boundaries are multiples of 4, so predicates are float4-uniform.
    const bool inL  = (q0 >= 0) && (q0 < Ln);
    const bool own  = (lane >= 4) && (lane < 28);           // warp-owned 96
    const bool pOut = own && (q0 >= s0) && (q0 < s0 + SEG); // block-owned 1024

    __shared__ float ys[WR];
    if (tid < WR / 4) ((float4*)ys)[tid] = make_float4(0.f, 0.f, 0.f, 0.f);

    float f0 = 0.f, f1 = 0.f, f2 = 0.f, f3 = 0.f;
    float l0 = 0.f, l1 = 0.f, l2 = 0.f, l3 = 0.f;
    float e0 = 10.f, e1 = 10.f, e2 = 10.f, e3 = 10.f;  // V_E / ALPHA_E
    float y0, y1, y2, y3;

    const float4* xp = (const float4*)(x   + (size_t)(b * Tn) * Ln) + (q0 >> 2);
    float4*       op = (float4*)      (out + (size_t)(b * Tn) * Ln) + (q0 >> 2);

    float4 xv = inL ? __ldg(xp) : make_float4(0.f, 0.f, 0.f, 0.f);
    xp += (Ln / 4);
    __syncthreads();  // smem init visible

    auto onestep = [&](float& f, float& l, float& e,
                       float y, float ym, float yp, float xj) -> float {
        const float conv = fmaf(w0, ym, fmaf(w1, y, w2 * yp));
        f = fmaf(df, f, xj) + conv;
        l = fmaf(dl, l, ym + yp);
        const float u = f * fmaf(0.5f, l, 1.0f);
        e = fmaf(de, e, Ve * y);
        const float z = u - e;
        return __fdividef(1.0f, 1.0f + __expf(-z));
    };

    int t = 0;
#pragma unroll 1
    for (int c = 0; c < Tn / TC; ++c) {
        // chunk start: reload full 128-wide warp region (incl. 16-halo each side)
        float4 yv = *(const float4*)&ys[off];
        y0 = yv.x; y1 = yv.y; y2 = yv.z; y3 = yv.w;
        __syncthreads();  // all loads done before chunk-end overwrites

#pragma unroll
        for (int s = 0; s < TC; ++s) {
            // prefetch next step's x
            float4 xn = make_float4(0.f, 0.f, 0.f, 0.f);
            if (inL && t + 1 < Tn) xn = __ldg(xp);

            // neighbor exchange: only lane-edge elements cross threads
            const float yl = __shfl_up_sync(0xffffffffu, y3, 1);   // lane0: garbage (cone-safe)
            const float yr = __shfl_down_sync(0xffffffffu, y0, 1); // lane31: garbage (cone-safe)

            float ny0 = onestep(f0, l0, e0, y0, yl, y1, xv.x);
            float ny1 = onestep(f1, l1, e1, y1, y0, y2, xv.y);
            float ny2 = onestep(f2, l2, e2, y2, y1, y3, xv.z);
            float ny3 = onestep(f3, l3, e3, y3, y2, yr, xv.w);

            // positions outside [0,L) emulate the zero pad
            if (!inL) { ny0 = 0.f; ny1 = 0.f; ny2 = 0.f; ny3 = 0.f; }

            if (pOut) *op = make_float4(ny0, ny1, ny2, ny3);
            op += (Ln / 4);

            y0 = ny0; y1 = ny1; y2 = ny2; y3 = ny3;
            xv = xn;
            xp += (Ln / 4);
            ++t;
        }

        // chunk end: publish owned 96 (lanes 4..27) back to SMEM
        if (own) *(float4*)&ys[off] = make_float4(y0, y1, y2, y3);
        __syncthreads();
    }
}

extern "C" void kernel_launch(void* const* d_in, const int* in_sizes, int n_in,
                              void* d_out, int out_size)
{
    const float* x = (const float*)d_in[0];   // [32, 64, 8192] f32
    const float* w = (const float*)d_in[1];   // [3] f32
    float* out = (float*)d_out;               // [32, 64, 8192] f32

    dim3 grid(Ln / SEG, Bn);   // (8, 32) = 256 blocks of 384 threads
    pcnn_kernel<<<grid, NTH>>>(x, w, out);
}

// round 5
// speedup vs baseline: 1.6221x; 1.1712x over previous
#include <cuda_runtime.h>

// PCNN recurrence B=32, T=64, L=8192 — time-chunked warp-autonomous trapezoids,
// packed f32x2 math + MUFU tanh sigmoid.
//
// Same decomposition as R4 (SEG=1024, region 1184, TC=16, NW=12), but the
// per-element math runs on the dual-fp32 pipe (fma.rn.f32x2) with state held
// as 4 packed pairs, and sigmoid(z) = 0.5 + 0.5*tanh(z/2) with z/2 obtained
// free by tracking u/2 and -e/2.

#define Tn   64
#define Ln   8192
#define Bn   32
#define SEG  1024
#define TC   16
#define NW   12
#define WR   (96 * NW + 32)     // 1184 region cells
#define NTH  (NW * 32)          // 384

typedef unsigned long long u64;

__device__ __forceinline__ u64 pk(float lo, float hi) {
    u64 r; asm("mov.b64 %0,{%1,%2};" : "=l"(r) : "f"(lo), "f"(hi)); return r;
}
__device__ __forceinline__ void upk(u64 v, float& lo, float& hi) {
    asm("mov.b64 {%0,%1},%2;" : "=f"(lo), "=f"(hi) : "l"(v));
}
__device__ __forceinline__ u64 fma2(u64 a, u64 b, u64 c) {
    u64 d; asm("fma.rn.f32x2 %0,%1,%2,%3;" : "=l"(d) : "l"(a), "l"(b), "l"(c)); return d;
}
__device__ __forceinline__ u64 add2(u64 a, u64 b) {
    u64 d; asm("add.rn.f32x2 %0,%1,%2;" : "=l"(d) : "l"(a), "l"(b)); return d;
}
__device__ __forceinline__ u64 mul2(u64 a, u64 b) {
    u64 d; asm("mul.rn.f32x2 %0,%1,%2;" : "=l"(d) : "l"(a), "l"(b)); return d;
}
__device__ __forceinline__ float tanhap(float z) {
    float r; asm("tanh.approx.f32 %0,%1;" : "=f"(r) : "f"(z)); return r;
}

__global__ __launch_bounds__(NTH, 2)
void pcnn_kernel(const float* __restrict__ x,
                 const float* __restrict__ w,
                 float* __restrict__ out)
{
    const int tid  = threadIdx.x;
    const int warp = tid >> 5;
    const int lane = tid & 31;
    const int b    = blockIdx.y;
    const int s0   = blockIdx.x * SEG;
    const int off  = 96 * warp + 4 * lane;   // region-rel base of 4 elems
    const int q0   = s0 - 80 + off;          // absolute position of elem 0

    const float w0s = __ldg(&w[0]);
    const float w1s = __ldg(&w[1]);
    const float w2s = __ldg(&w[2]);

    const u64 W0 = pk(w0s, w0s), W1 = pk(w1s, w1s), W2 = pk(w2s, w2s);
    const u64 DF = pk(0.90483741803595952f, 0.90483741803595952f);  // exp(-0.1)
    const u64 DL = pk(0.36787944117144233f, 0.36787944117144233f);  // exp(-1)
    const u64 DE = DL;
    const u64 Q  = pk(0.25f, 0.25f);
    const u64 H  = pk(0.5f, 0.5f);
    const u64 NVH = pk(-5.0f, -5.0f);        // -(V_E)/2

    const bool inL  = (q0 >= 0) && (q0 < Ln);
    const bool own  = (lane >= 4) && (lane < 28);
    const bool pOut = own && (q0 >= s0) && (q0 < s0 + SEG);

    // clamped x address (always safe to load; garbage only feeds !inL lanes)
    int qc = q0 < 0 ? 0 : (q0 > Ln - 4 ? Ln - 4 : q0);
    const ulonglong2* xrow = (const ulonglong2*)(x + (size_t)(b * Tn) * Ln) + (qc >> 2);
    ulonglong2*       op   = (ulonglong2*)(out + (size_t)(b * Tn) * Ln) + (q0 >> 2);

    __shared__ float ys[WR];
    if (tid < WR / 4) ((float4*)ys)[tid] = make_float4(0.f, 0.f, 0.f, 0.f);

    u64 F01 = 0, F23 = 0, L01 = 0, L23 = 0;
    u64 E01 = pk(-5.f, -5.f), E23 = pk(-5.f, -5.f);   // En = -e/2, e0 = V_E/ALPHA_E = 10
    u64 Y01 = 0, Y23 = 0;

    ulonglong2 xv = __ldg(xrow);   // x at t=0
    __syncthreads();               // smem init visible

    int t = 0;
#pragma unroll 1
    for (int c = 0; c < Tn / TC; ++c) {
        // chunk start: reload full 128-wide warp region from smem
        {
            ulonglong2 yv = *(const ulonglong2*)&ys[off];
            Y01 = yv.x; Y23 = yv.y;
        }
        __syncthreads();

#pragma unroll
        for (int s = 0; s < TC; ++s) {
            // prefetch x for next step (clamped at t=63; value unused then)
            const int tn = (t + 1 < Tn) ? (t + 1) : (Tn - 1);
            const ulonglong2 xn = __ldg(xrow + (size_t)tn * (Ln / 4));

            float y0, y1, y2, y3;
            upk(Y01, y0, y1); upk(Y23, y2, y3);
            const float yl = __shfl_up_sync(0xffffffffu, y3, 1);   // lane0 garbage: cone-safe
            const float yr = __shfl_down_sync(0xffffffffu, y0, 1); // lane31 garbage: cone-safe

            const u64 A = pk(yl, y0);
            const u64 B = pk(y1, y2);       // shared: yp of pair01, ym of pair23
            const u64 C = pk(y3, yr);

            // f = df*f + x + (w0*ym + w1*y + w2*yp)
            const u64 cv0 = fma2(W0, A, fma2(W1, Y01, mul2(W2, B)));
            const u64 cv1 = fma2(W0, B, fma2(W1, Y23, mul2(W2, C)));
            F01 = add2(fma2(DF, F01, xv.x), cv0);
            F23 = add2(fma2(DF, F23, xv.y), cv1);

            // l = dl*l + ym + yp
            L01 = fma2(DL, L01, add2(A, B));
            L23 = fma2(DL, L23, add2(B, C));

            // u/2 = f * (0.25*l + 0.5)
            const u64 U0 = mul2(F01, fma2(Q, L01, H));
            const u64 U1 = mul2(F23, fma2(Q, L23, H));

            // En = de*En - 5*y   (En = -e/2)
            E01 = fma2(DE, E01, mul2(NVH, Y01));
            E23 = fma2(DE, E23, mul2(NVH, Y23));

            // z/2 = u/2 + En ;  y = 0.5 + 0.5*tanh(z/2)
            float z0, z1, z2, z3;
            upk(add2(U0, E01), z0, z1);
            upk(add2(U1, E23), z2, z3);
            Y01 = fma2(H, pk(tanhap(z0), tanhap(z1)), H);
            Y23 = fma2(H, pk(tanhap(z2), tanhap(z3)), H);

            // positions outside [0,L) emulate the zero pad
            if (!inL) { Y01 = 0; Y23 = 0; }

            if (pOut) { ulonglong2 o; o.x = Y01; o.y = Y23; *op = o; }
            op += (Ln / 4);

            xv = xn;
            ++t;
        }

        // chunk end: publish owned 96 (lanes 4..27)
        if (own) { ulonglong2 o; o.x = Y01; o.y = Y23; *(ulonglong2*)&ys[off] = o; }
        __syncthreads();
    }
}

extern "C" void kernel_launch(void* const* d_in, const int* in_sizes, int n_in,
                              void* d_out, int out_size)
{
    const float* x = (const float*)d_in[0];   // [32, 64, 8192] f32
    const float* w = (const float*)d_in[1];   // [3] f32
    float* out = (float*)d_out;               // [32, 64, 8192] f32

    dim3 grid(Ln / SEG, Bn);   // (8, 32) = 256 blocks of 384 threads
    pcnn_kernel<<<grid, NTH>>>(x, w, out);
}